// round 3
// baseline (speedup 1.0000x reference)
#include <cuda_runtime.h>
#include <math.h>

// Fixed shapes
#define BN 8192
#define DN 2048
#define TINV 10.0f           // 1/T, T = 0.1
#define NTHR 256             // threads/block -> 8 warps -> 8 rows/block
#define WPB  (NTHR / 32)     // 8
#define NBLK (BN / WPB)      // 1024

// Scratch (device globals)
__device__ double g_partE[NBLK];
__device__ double g_partW[NBLK];
__device__ double g_partL[NBLK];
__device__ unsigned int g_count;

__device__ __forceinline__ float warp_sum(float v) {
    #pragma unroll
    for (int o = 16; o; o >>= 1) v += __shfl_xor_sync(0xffffffffu, v, o);
    return v;
}
__device__ __forceinline__ double warp_sum_d(double v) {
    #pragma unroll
    for (int o = 16; o; o >>= 1) v += __shfl_xor_sync(0xffffffffu, v, o);
    return v;
}

__global__ void __launch_bounds__(NTHR, 4)
fused_kernel(const float* __restrict__ embed,
             const float* __restrict__ ee,
             const float* __restrict__ labels,
             float* __restrict__ out) {
    __shared__ float4  sa[DN / 4];            // RAW anchor, 8 KB
    __shared__ float   redf[WPB];             // per-warp partial ||e0||^2
    __shared__ double  redE[WPB], redW[WPB], redL[WPB];
    __shared__ bool    s_last;

    const int tid  = threadIdx.x;
    const int warp = tid >> 5;
    const int lane = tid & 31;

    // ---- Stage RAW anchor into shared; accumulate ||e0||^2 partials.
    //      Exactly ONE sync before the stream. ----
    const float4* e4 = reinterpret_cast<const float4*>(embed);
    float s = 0.f;
    #pragma unroll
    for (int i = 0; i < (DN / 4) / NTHR; i++) {      // 2 iterations
        float4 v = e4[i * NTHR + tid];
        sa[i * NTHR + tid] = v;
        s = fmaf(v.x, v.x, s);
        s = fmaf(v.y, v.y, s);
        s = fmaf(v.z, v.z, s);
        s = fmaf(v.w, v.w, s);
    }
    s = warp_sum(s);
    if (lane == 0) redf[warp] = s;
    __syncthreads();

    // ---- Streaming phase: one warp per row, fully unrolled 16x float4 ----
    const int row = blockIdx.x * WPB + warp;
    const float4* x4 = reinterpret_cast<const float4*>(ee + (size_t)row * DN);

    float dot = 0.f, n2 = 0.f;
    #pragma unroll
    for (int i = 0; i < DN / (4 * 32); i++) {        // 16 float4 loads/lane
        float4 x  = x4[i * 32 + lane];
        float4 aa = sa[i * 32 + lane];
        dot = fmaf(x.x, aa.x, dot);
        dot = fmaf(x.y, aa.y, dot);
        dot = fmaf(x.z, aa.z, dot);
        dot = fmaf(x.w, aa.w, dot);
        n2  = fmaf(x.x, x.x, n2);
        n2  = fmaf(x.y, x.y, n2);
        n2  = fmaf(x.z, x.z, n2);
        n2  = fmaf(x.w, x.w, n2);
    }
    dot = warp_sum(dot);
    n2  = warp_sum(n2);

    // ---- Per-warp epilogue (lane 0). Anchor scalars computed here, after
    //      the stream; redf was finalized before the single sync. ----
    if (lane == 0) {
        double E = 0.0, W = 0.0, L = 0.0;
        if (row != 0) {
            float anorm2 = 0.f;
            #pragma unroll
            for (int i = 0; i < WPB; i++) anorm2 += redf[i];
            float norm0 = sqrtf(anorm2);
            float inv   = 1.0f / fmaxf(norm0, 1e-12f);
            float na    = fmaxf(norm0 * inv, 1e-6f);   // ~1.0, faithful scale
            float nb    = fmaxf(sqrtf(n2), 1e-6f);
            float neg   = -TINV * dot * inv / (na * nb);
            float lj    = labels[row];
            E = (double)expf(neg);
            W = (double)lj * (double)neg;
            L = (double)lj;
        }
        redE[warp] = E; redW[warp] = W; redL[warp] = L;
    }
    __syncthreads();

    // ---- Block partials -> scratch ----
    if (warp == 0) {
        double E = (lane < WPB) ? redE[lane] : 0.0;
        double W = (lane < WPB) ? redW[lane] : 0.0;
        double L = (lane < WPB) ? redL[lane] : 0.0;
        E = warp_sum_d(E); W = warp_sum_d(W); L = warp_sum_d(L);
        if (lane == 0) {
            g_partE[blockIdx.x] = E;
            g_partW[blockIdx.x] = W;
            g_partL[blockIdx.x] = L;
            __threadfence();
            unsigned int c = atomicAdd(&g_count, 1u);
            s_last = (c == NBLK - 1);
        }
    }
    __syncthreads();

    // ---- Last block reduces 1024 partials and finalizes ----
    if (s_last) {
        double E = 0.0, W = 0.0, L = 0.0;
        #pragma unroll
        for (int k = 0; k < NBLK / NTHR; k++) {       // 4 slots per thread
            int idx = k * NTHR + tid;
            E += g_partE[idx]; W += g_partW[idx]; L += g_partL[idx];
        }
        E = warp_sum_d(E); W = warp_sum_d(W); L = warp_sum_d(L);
        if (lane == 0) { redE[warp] = E; redW[warp] = W; redL[warp] = L; }
        __syncthreads();
        if (tid == 0) {
            double Et = 0, Wt = 0, Lt = 0;
            #pragma unroll
            for (int i = 0; i < WPB; i++) { Et += redE[i]; Wt += redW[i]; Lt += redL[i]; }
            double l0   = (double)labels[0];
            double E0   = 1e-12 + Et;
            double C0   = 1e-12 + l0 * Lt;
            double logE = log(E0);
            double L0   = (l0 / C0) * (logE * Lt - Wt);
            out[0] = (float)(L0 / (double)BN);
            g_count = 0;                               // reset for replay
        }
    }
}

extern "C" void kernel_launch(void* const* d_in, const int* in_sizes, int n_in,
                              void* d_out, int out_size) {
    const float* embed         = (const float*)d_in[0];
    const float* embed_enhance = (const float*)d_in[1];
    const float* labels        = (const float*)d_in[2];
    float* out = (float*)d_out;

    fused_kernel<<<NBLK, NTHR>>>(embed, embed_enhance, labels, out);
}